// round 10
// baseline (speedup 1.0000x reference)
#include <cuda_runtime.h>

// YOLO v0 loss — R6 dataflow (verified optimum), 128-thread CTA revision.
//
// Mechanism learned over R6-R9: block TURNOVER is what keeps the SM load
// queue fed (fresh CTAs arrive with 10-load front batches). R10: halve CTA
// size (4 warps) so the slowest-warp gate on CTA retirement couples fewer
// warps and resources recycle ~2x more fluidly; 10 CTAs/SM resident.
// Dataflow, load order, and per-element math are byte-identical to R6.

#define LAMBDA_COOR  5.0f
#define LAMBDA_NOOBJ 0.5f

static const int TOTAL_CELLS     = 128 * 256 * 256;          // 8,388,608
static const int BLOCK           = 128;                      // 4 warps
static const int WARPS           = BLOCK / 32;
static const int FLOATS_PER_WARP = 640;                      // 128 cells, %5==0
static const int CELLS_PER_BLOCK = WARPS * 128;              // 512
static const int GRID            = TOTAL_CELLS / CELLS_PER_BLOCK;  // 16384

__device__ float        g_partials[GRID];
__device__ unsigned int g_done_count = 0;

__device__ __forceinline__ float block_reduce(float acc, float* s_warp) {
#pragma unroll
    for (int off = 16; off > 0; off >>= 1)
        acc += __shfl_down_sync(0xFFFFFFFFu, acc, off);
    int lane = threadIdx.x & 31;
    int wid  = threadIdx.x >> 5;
    if (lane == 0) s_warp[wid] = acc;
    __syncthreads();
    float v = 0.0f;
    if (wid == 0) {
        v = (lane < WARPS) ? s_warp[lane] : 0.0f;
#pragma unroll
        for (int off = 2; off > 0; off >>= 1)
            v += __shfl_down_sync(0xFFFFFFFFu, v, off);
    }
    return v;   // valid in thread 0 only
}

__global__ __launch_bounds__(BLOCK, 10)   // 10 CTAs/SM, regs capped at 51
void yolo_loss_fused(const float* __restrict__ out, const float* __restrict__ tgt,
                     float* __restrict__ d_loss) {
    const int lane = threadIdx.x & 31;
    const int wid  = threadIdx.x >> 5;

    const size_t warp_gid = (size_t)blockIdx.x * WARPS + wid;
    const size_t base_f   = warp_gid * FLOATS_PER_WARP;      // % 5 == 0

    const float4* ob = reinterpret_cast<const float4*>(out) + base_f / 4 + lane;
    const float4* tb = reinterpret_cast<const float4*>(tgt) + base_f / 4 + lane;

    // ---- 10 fully-coalesced streaming LDG.128, front-batched (MLP=10) ----
    float4 ao[5], at[5];
#pragma unroll
    for (int j = 0; j < 5; j++) ao[j] = __ldcs(ob + j * 32);
#pragma unroll
    for (int j = 0; j < 5; j++) at[j] = __ldcs(tb + j * 32);

    // c0(j) = (4*lane + 3j) % 5, advanced incrementally.
    int c0 = (4 * lane) % 5;

    const unsigned FULL = 0xFFFFFFFFu;
    float acc = 0.0f;
    float rot_prev = 0.0f;   // lane-0 wraparound source from chunk j-1

#pragma unroll
    for (int j = 0; j < 5; j++) {
        const float4 a = ao[j];
        const float4 t = at[j];

        // confB: conf of the 2nd cell in this float4 (valid when c0>=2);
        // doubles as the shuffle payload for all c0>=1.
        const float confB = (c0 == 2) ? t.w : (c0 == 3) ? t.z : t.y;
        const float send  = (c0 == 0) ? t.x : confB;
        const float rot   = __shfl_sync(FULL, send, (lane + 31) & 31);

        // cellA conf: own t.x if c0==0, else lane-1's payload
        // (lane 0 takes chunk j-1's lane-31 payload).
        const float confA = (c0 == 0) ? t.x : (lane != 0 ? rot : rot_prev);
        rot_prev = rot;

        const bool mA = confA > 0.0f;
        const bool mB = confB > 0.0f;

        const float wA5 = mA ? LAMBDA_COOR : 0.0f;
        const float wB5 = mB ? LAMBDA_COOR : 0.0f;
        const bool  mC  = (c0 == 0) ? mA : mB;     // mask of conf element's cell
        const float wc  = mC ? 1.0f : LAMBDA_NOOBJ;
        const float sc  = mC ? 1.0f : 0.0f;

        const float fo[4] = {a.x, a.y, a.z, a.w};
        const float ft[4] = {t.x, t.y, t.z, t.w};

#pragma unroll
        for (int k = 0; k < 4; k++) {
            // element k in cellA iff c0 + k < 5; conf element iff
            // c0 == (5-k)%5  (k=0:c0==0, k=1:c0==4, k=2:c0==3, k=3:c0==2).
            const bool isA    = (c0 <= 4 - k);
            const bool isconf = (c0 == ((5 - k) % 5));
            const float w = isconf ? wc : (isA ? wA5 : wB5);
            const float s = isconf ? sc : ft[k];
            const float d = fo[k] - s;
            acc = fmaf(w, d * d, acc);
        }

        c0 += 3; if (c0 >= 5) c0 -= 5;
    }

    __shared__ float s_warp[WARPS];
    __shared__ bool  s_is_last;
    float bsum = block_reduce(acc, s_warp);

    if (threadIdx.x == 0) {
        g_partials[blockIdx.x] = bsum;
        __threadfence();
        unsigned int n = atomicAdd(&g_done_count, 1u);
        s_is_last = (n == (unsigned int)(GRID - 1));
    }
    __syncthreads();

    if (s_is_last) {
        float tsum = 0.0f;
        for (int i = threadIdx.x; i < GRID; i += BLOCK)
            tsum += g_partials[i];
        float total = block_reduce(tsum, s_warp);
        if (threadIdx.x == 0) {
            d_loss[0] = total * (1.0f / 128.0f);
            g_done_count = 0;                  // reset for next graph replay
        }
    }
}

extern "C" void kernel_launch(void* const* d_in, const int* in_sizes, int n_in,
                              void* d_out, int out_size) {
    const float* outputs = (const float*)d_in[0];
    const float* targets = (const float*)d_in[1];
    float* loss = (float*)d_out;

    yolo_loss_fused<<<GRID, BLOCK>>>(outputs, targets, loss);
}

// round 11
// speedup vs baseline: 1.0702x; 1.0702x over previous
#include <cuda_runtime.h>

// YOLO v0 loss — R6 mainloop byte-identical (verified optimum: 53.8us,
// DRAM 80.5%, queue-saturated at ~6.4TB/s delivered), with the serialized
// tail removed: block sums go into one u64 fixed-point accumulator
// (deterministic: integer adds are associative), last block converts and
// writes the scalar. No 8192-partial fold at the end.
//
// CTA-size gradient measured: 128thr=56.4us, 256thr=53.2us; pipeline (R7),
// persistent grid (R8), t-first reorder (R9) all regress. Block turnover
// with a 10-wide front batch is the winning structure.

#define LAMBDA_COOR  5.0f
#define LAMBDA_NOOBJ 0.5f

static const int TOTAL_CELLS     = 128 * 256 * 256;          // 8,388,608
static const int BLOCK           = 256;                      // 8 warps
static const int WARPS           = BLOCK / 32;
static const int FLOATS_PER_WARP = 640;                      // 128 cells, %5==0
static const int CELLS_PER_BLOCK = WARPS * 128;              // 1024
static const int GRID            = TOTAL_CELLS / CELLS_PER_BLOCK;  // 8192

#define FIXED_SCALE 65536.0            // 2^16 fixed-point for deterministic sum

__device__ unsigned long long g_total_fx   = 0ull;
__device__ unsigned int       g_done_count = 0;

__device__ __forceinline__ float block_reduce(float acc, float* s_warp) {
#pragma unroll
    for (int off = 16; off > 0; off >>= 1)
        acc += __shfl_down_sync(0xFFFFFFFFu, acc, off);
    int lane = threadIdx.x & 31;
    int wid  = threadIdx.x >> 5;
    if (lane == 0) s_warp[wid] = acc;
    __syncthreads();
    float v = 0.0f;
    if (wid == 0) {
        v = (lane < WARPS) ? s_warp[lane] : 0.0f;
#pragma unroll
        for (int off = 4; off > 0; off >>= 1)
            v += __shfl_down_sync(0xFFFFFFFFu, v, off);
    }
    return v;   // valid in thread 0 only
}

__global__ __launch_bounds__(BLOCK, 5)   // 5 blocks/SM, regs capped at 51
void yolo_loss_fused(const float* __restrict__ out, const float* __restrict__ tgt,
                     float* __restrict__ d_loss) {
    const int lane = threadIdx.x & 31;
    const int wid  = threadIdx.x >> 5;

    const size_t warp_gid = (size_t)blockIdx.x * WARPS + wid;
    const size_t base_f   = warp_gid * FLOATS_PER_WARP;      // % 5 == 0

    const float4* ob = reinterpret_cast<const float4*>(out) + base_f / 4 + lane;
    const float4* tb = reinterpret_cast<const float4*>(tgt) + base_f / 4 + lane;

    // ---- 10 fully-coalesced streaming LDG.128, front-batched (MLP=10) ----
    float4 ao[5], at[5];
#pragma unroll
    for (int j = 0; j < 5; j++) ao[j] = __ldcs(ob + j * 32);
#pragma unroll
    for (int j = 0; j < 5; j++) at[j] = __ldcs(tb + j * 32);

    // c0(j) = (4*lane + 3j) % 5, advanced incrementally.
    int c0 = (4 * lane) % 5;

    const unsigned FULL = 0xFFFFFFFFu;
    float acc = 0.0f;
    float rot_prev = 0.0f;   // lane-0 wraparound source from chunk j-1

#pragma unroll
    for (int j = 0; j < 5; j++) {
        const float4 a = ao[j];
        const float4 t = at[j];

        // confB: conf of the 2nd cell in this float4 (valid when c0>=2);
        // doubles as the shuffle payload for all c0>=1.
        const float confB = (c0 == 2) ? t.w : (c0 == 3) ? t.z : t.y;
        const float send  = (c0 == 0) ? t.x : confB;
        const float rot   = __shfl_sync(FULL, send, (lane + 31) & 31);

        // cellA conf: own t.x if c0==0, else lane-1's payload
        // (lane 0 takes chunk j-1's lane-31 payload).
        const float confA = (c0 == 0) ? t.x : (lane != 0 ? rot : rot_prev);
        rot_prev = rot;

        const bool mA = confA > 0.0f;
        const bool mB = confB > 0.0f;

        const float wA5 = mA ? LAMBDA_COOR : 0.0f;
        const float wB5 = mB ? LAMBDA_COOR : 0.0f;
        const bool  mC  = (c0 == 0) ? mA : mB;     // mask of conf element's cell
        const float wc  = mC ? 1.0f : LAMBDA_NOOBJ;
        const float sc  = mC ? 1.0f : 0.0f;

        const float fo[4] = {a.x, a.y, a.z, a.w};
        const float ft[4] = {t.x, t.y, t.z, t.w};

#pragma unroll
        for (int k = 0; k < 4; k++) {
            // element k in cellA iff c0 + k < 5; conf element iff
            // c0 == (5-k)%5  (k=0:c0==0, k=1:c0==4, k=2:c0==3, k=3:c0==2).
            const bool isA    = (c0 <= 4 - k);
            const bool isconf = (c0 == ((5 - k) % 5));
            const float w = isconf ? wc : (isA ? wA5 : wB5);
            const float s = isconf ? sc : ft[k];
            const float d = fo[k] - s;
            acc = fmaf(w, d * d, acc);
        }

        c0 += 3; if (c0 >= 5) c0 -= 5;
    }

    __shared__ float s_warp[WARPS];
    __shared__ bool  s_is_last;
    float bsum = block_reduce(acc, s_warp);

    if (threadIdx.x == 0) {
        // Deterministic fixed-point accumulation (integer adds associative).
        // All loss terms are >= 0, so bsum >= 0.
        unsigned long long fx = __double2ull_rn((double)bsum * FIXED_SCALE);
        atomicAdd(&g_total_fx, fx);
        __threadfence();                       // sum visible before counter
        unsigned int n = atomicAdd(&g_done_count, 1u);
        s_is_last = (n == (unsigned int)(GRID - 1));
    }
    __syncthreads();

    if (s_is_last && threadIdx.x == 0) {
        unsigned long long total = atomicAdd(&g_total_fx, 0ull);  // coherent read
        d_loss[0] = (float)((double)total * (1.0 / FIXED_SCALE) * (1.0 / 128.0));
        g_total_fx   = 0ull;                   // reset for next graph replay
        g_done_count = 0;
    }
}

extern "C" void kernel_launch(void* const* d_in, const int* in_sizes, int n_in,
                              void* d_out, int out_size) {
    const float* outputs = (const float*)d_in[0];
    const float* targets = (const float*)d_in[1];
    float* loss = (float*)d_out;

    yolo_loss_fused<<<GRID, BLOCK>>>(outputs, targets, loss);
}